// round 1
// baseline (speedup 1.0000x reference)
#include <cuda_runtime.h>
#include <cuda_bf16.h>
#include <math.h>

#define NUM_EXPERTS 32
#define TOP_K 8
#define HIDDEN 1536
#define INTER 512
#define T_MAX 8192
#define CAP 8192   // worst-case tokens per expert

// ---------------- device scratch (no cudaMalloc allowed) ----------------
__device__ int   g_cnt[NUM_EXPERTS];
__device__ int   g_tok[NUM_EXPERTS * CAP];
__device__ float g_wt [NUM_EXPERTS * CAP];
// h = silu(g)*u, expert-major: [(e*CAP + r) * INTER + k]  (512 MB fp32)
__device__ float g_h[(size_t)NUM_EXPERTS * CAP * INTER];

// ---------------- kernel 0: zero output + counters ----------------
__global__ void zero_kernel(float* __restrict__ out, size_t n) {
    size_t i = (size_t)blockIdx.x * blockDim.x + threadIdx.x;
    size_t stride = (size_t)gridDim.x * blockDim.x;
    for (; i < n; i += stride) out[i] = 0.0f;
    if (blockIdx.x == 0 && threadIdx.x < NUM_EXPERTS) g_cnt[threadIdx.x] = 0;
}

// ---------------- kernel 1: router (one block per token) ----------------
__global__ void router_kernel(const float* __restrict__ x,
                              const float* __restrict__ gate_w) {
    const int t = blockIdx.x;
    const int tid = threadIdx.x;
    __shared__ float xs[HIDDEN];
    __shared__ float part[256];
    __shared__ float lg[NUM_EXPERTS];

    // load token row into smem (float4)
    for (int i = tid * 4; i < HIDDEN; i += 256 * 4) {
        *(float4*)&xs[i] = *(const float4*)&x[(size_t)t * HIDDEN + i];
    }
    __syncthreads();

    // 8 partials per expert
    const int e = tid & 31;
    const int p = tid >> 5;            // 0..7, each covers 192 elements
    const float* gw = gate_w + (size_t)e * HIDDEN + p * 192;
    const float* xp = xs + p * 192;
    float s = 0.0f;
    #pragma unroll 4
    for (int i = 0; i < 192; i++) s += xp[i] * gw[i];
    part[tid] = s;
    __syncthreads();

    if (tid < NUM_EXPERTS) {
        float l = 0.0f;
        #pragma unroll
        for (int q = 0; q < 8; q++) l += part[q * 32 + tid];
        lg[tid] = l;
    }
    __syncthreads();

    if (tid == 0) {
        // softmax numerator only: top-8 renorm cancels the denominator
        float mx = -INFINITY;
        #pragma unroll
        for (int i = 0; i < NUM_EXPERTS; i++) mx = fmaxf(mx, lg[i]);
        float pr[NUM_EXPERTS];
        #pragma unroll
        for (int i = 0; i < NUM_EXPERTS; i++) pr[i] = expf(lg[i] - mx);

        int idx[TOP_K]; float w[TOP_K]; float ws = 0.0f;
        unsigned used = 0u;
        for (int k = 0; k < TOP_K; k++) {
            int bi = -1; float bv = -INFINITY;
            for (int i = 0; i < NUM_EXPERTS; i++) {
                if (!(used >> i & 1u) && pr[i] > bv) { bv = pr[i]; bi = i; }
            }
            used |= 1u << bi; idx[k] = bi; w[k] = bv; ws += bv;
        }
        float inv = 1.0f / ws;
        for (int k = 0; k < TOP_K; k++) {
            int slot = atomicAdd(&g_cnt[idx[k]], 1);
            g_tok[idx[k] * CAP + slot] = t;
            g_wt [idx[k] * CAP + slot] = w[k] * inv;
        }
    }
}

// ---------------- kernel 2: grouped GEMM1 + SiLU ----------------
// C_g[r,c] = sum_k X[tok[r],k] * w13[e, c, k];  C_u uses c+512.
// h[r,c] = silu(C_g)*C_u  -> g_h
__global__ void __launch_bounds__(256) gemm1_silu_kernel(
        const float* __restrict__ x, const float* __restrict__ w13) {
    const int e = blockIdx.z;
    const int rows = g_cnt[e];
    const int rt = blockIdx.x;
    if (rt * 64 >= rows) return;
    const int ct = blockIdx.y;            // 0..7 -> cols ct*64 of g/u

    __shared__ float As[16][68];
    __shared__ float Bg[16][68];
    __shared__ float Bu[16][68];

    const int tid = threadIdx.x;
    const int lr = tid >> 2;              // 0..63
    const int lk = (tid & 3) * 4;         // 0,4,8,12
    const int tx = tid & 15, ty = tid >> 4;

    const int arow = rt * 64 + lr;
    const float* xrow = nullptr;
    if (arow < rows) xrow = x + (size_t)g_tok[e * CAP + arow] * HIDDEN;
    const float* bgrow = w13 + ((size_t)e * 1024 + (size_t)ct * 64 + lr) * HIDDEN;
    const float* burow = bgrow + (size_t)INTER * HIDDEN;

    float accg[4][4] = {}, accu[4][4] = {};

    for (int k0 = 0; k0 < HIDDEN; k0 += 16) {
        float4 av = make_float4(0.f, 0.f, 0.f, 0.f);
        if (xrow) av = *(const float4*)(xrow + k0 + lk);
        float4 bgv = *(const float4*)(bgrow + k0 + lk);
        float4 buv = *(const float4*)(burow + k0 + lk);
        __syncthreads();
        As[lk+0][lr]=av.x;  As[lk+1][lr]=av.y;  As[lk+2][lr]=av.z;  As[lk+3][lr]=av.w;
        Bg[lk+0][lr]=bgv.x; Bg[lk+1][lr]=bgv.y; Bg[lk+2][lr]=bgv.z; Bg[lk+3][lr]=bgv.w;
        Bu[lk+0][lr]=buv.x; Bu[lk+1][lr]=buv.y; Bu[lk+2][lr]=buv.z; Bu[lk+3][lr]=buv.w;
        __syncthreads();
        #pragma unroll
        for (int k = 0; k < 16; k++) {
            float4 a4 = *(const float4*)&As[k][ty * 4];
            float4 g4 = *(const float4*)&Bg[k][tx * 4];
            float4 u4 = *(const float4*)&Bu[k][tx * 4];
            float aa[4] = {a4.x, a4.y, a4.z, a4.w};
            float gg[4] = {g4.x, g4.y, g4.z, g4.w};
            float uu[4] = {u4.x, u4.y, u4.z, u4.w};
            #pragma unroll
            for (int i = 0; i < 4; i++)
                #pragma unroll
                for (int j = 0; j < 4; j++) {
                    accg[i][j] = fmaf(aa[i], gg[j], accg[i][j]);
                    accu[i][j] = fmaf(aa[i], uu[j], accu[i][j]);
                }
        }
    }

    #pragma unroll
    for (int i = 0; i < 4; i++) {
        int gr = rt * 64 + ty * 4 + i;
        if (gr >= rows) continue;
        float* hrow = g_h + ((size_t)e * CAP + gr) * INTER + ct * 64 + tx * 4;
        #pragma unroll
        for (int j = 0; j < 4; j++) {
            float g = accg[i][j], u = accu[i][j];
            hrow[j] = g * u / (1.0f + expf(-g));   // silu(g)*u
        }
    }
}

// ---------------- kernel 3: grouped GEMM2 + weighted scatter ----------------
// Y[r,c] = sum_k h[r,k] * w2[e, c, k];  out[tok[r], c] += wt[r] * Y[r,c]
__global__ void __launch_bounds__(256) gemm2_scatter_kernel(
        const float* __restrict__ w2, float* __restrict__ out) {
    const int e = blockIdx.z;
    const int rows = g_cnt[e];
    const int rt = blockIdx.x;
    if (rt * 64 >= rows) return;
    const int ct = blockIdx.y;            // 0..23 -> out cols ct*64

    __shared__ float As[16][68];
    __shared__ float Bs[16][68];

    const int tid = threadIdx.x;
    const int lr = tid >> 2;
    const int lk = (tid & 3) * 4;
    const int tx = tid & 15, ty = tid >> 4;

    const int arow = rt * 64 + lr;
    const float* hrow = nullptr;
    if (arow < rows) hrow = g_h + ((size_t)e * CAP + arow) * INTER;
    const float* brow = w2 + ((size_t)e * HIDDEN + (size_t)ct * 64 + lr) * INTER;

    float acc[4][4] = {};

    for (int k0 = 0; k0 < INTER; k0 += 16) {
        float4 av = make_float4(0.f, 0.f, 0.f, 0.f);
        if (hrow) av = *(const float4*)(hrow + k0 + lk);
        float4 bv = *(const float4*)(brow + k0 + lk);
        __syncthreads();
        As[lk+0][lr]=av.x; As[lk+1][lr]=av.y; As[lk+2][lr]=av.z; As[lk+3][lr]=av.w;
        Bs[lk+0][lr]=bv.x; Bs[lk+1][lr]=bv.y; Bs[lk+2][lr]=bv.z; Bs[lk+3][lr]=bv.w;
        __syncthreads();
        #pragma unroll
        for (int k = 0; k < 16; k++) {
            float4 a4 = *(const float4*)&As[k][ty * 4];
            float4 b4 = *(const float4*)&Bs[k][tx * 4];
            float aa[4] = {a4.x, a4.y, a4.z, a4.w};
            float bb[4] = {b4.x, b4.y, b4.z, b4.w};
            #pragma unroll
            for (int i = 0; i < 4; i++)
                #pragma unroll
                for (int j = 0; j < 4; j++)
                    acc[i][j] = fmaf(aa[i], bb[j], acc[i][j]);
        }
    }

    #pragma unroll
    for (int i = 0; i < 4; i++) {
        int gr = rt * 64 + ty * 4 + i;
        if (gr >= rows) continue;
        int tokr = g_tok[e * CAP + gr];
        float wgt = g_wt[e * CAP + gr];
        float* orow = out + (size_t)tokr * HIDDEN + ct * 64 + tx * 4;
        #pragma unroll
        for (int j = 0; j < 4; j++)
            atomicAdd(&orow[j], wgt * acc[i][j]);
    }
}

// ---------------- launch ----------------
extern "C" void kernel_launch(void* const* d_in, const int* in_sizes, int n_in,
                              void* d_out, int out_size) {
    const float* x      = (const float*)d_in[0];   // (4,2048,1536)
    const float* gate_w = (const float*)d_in[1];   // (32,1536)
    const float* w13    = (const float*)d_in[2];   // (32,1024,1536)
    const float* w2     = (const float*)d_in[3];   // (32,1536,512)
    float* out = (float*)d_out;

    zero_kernel<<<2048, 256>>>(out, (size_t)out_size);
    router_kernel<<<T_MAX, 256>>>(x, gate_w);
    gemm1_silu_kernel<<<dim3(T_MAX / 64, INTER / 64, NUM_EXPERTS), 256>>>(x, w13);
    gemm2_scatter_kernel<<<dim3(T_MAX / 64, HIDDEN / 64, NUM_EXPERTS), 256>>>(w2, out);
}

// round 3
// speedup vs baseline: 1.7338x; 1.7338x over previous
#include <cuda_runtime.h>
#include <cuda_bf16.h>
#include <cstdint>
#include <math.h>

#define NUM_EXPERTS 32
#define TOP_K 8
#define HIDDEN 1536
#define INTER 512
#define T_TOT 8192
#define CAP 8192
#define ROWS_TOT (T_TOT * TOP_K)

// ---------------- device scratch ----------------
__device__ int   g_cnt[NUM_EXPERTS];
__device__ int   g_off[NUM_EXPERTS];
__device__ int   g_tok[NUM_EXPERTS * CAP];
__device__ float g_wt [NUM_EXPERTS * CAP];
__device__ int   g_pair[T_TOT * TOP_K];

__device__ __nv_bfloat16 g_xh[(size_t)T_TOT * HIDDEN];
__device__ __nv_bfloat16 g_xl[(size_t)T_TOT * HIDDEN];
__device__ __nv_bfloat16 g_w13h[(size_t)NUM_EXPERTS * 2 * INTER * HIDDEN];
__device__ __nv_bfloat16 g_w13l[(size_t)NUM_EXPERTS * 2 * INTER * HIDDEN];
__device__ __nv_bfloat16 g_w2h[(size_t)NUM_EXPERTS * HIDDEN * INTER];
__device__ __nv_bfloat16 g_w2l[(size_t)NUM_EXPERTS * HIDDEN * INTER];
__device__ __nv_bfloat16 g_hh[(size_t)ROWS_TOT * INTER];
__device__ __nv_bfloat16 g_hl[(size_t)ROWS_TOT * INTER];
__device__ float g_y[(size_t)ROWS_TOT * HIDDEN];

// ---------------- helpers ----------------
__device__ __forceinline__ uint32_t smem_u32(const void* p) {
    uint32_t a;
    asm("{ .reg .u64 t; cvta.to.shared.u64 t, %1; cvt.u32.u64 %0, t; }" : "=r"(a) : "l"(p));
    return a;
}
__device__ __forceinline__ void cp16(uint32_t dst, const void* src, int sz) {
    asm volatile("cp.async.cg.shared.global [%0], [%1], 16, %2;"
                 :: "r"(dst), "l"(__cvta_generic_to_global(src)), "r"(sz));
}
#define CP_COMMIT() asm volatile("cp.async.commit_group;")
#define CP_WAIT1()  asm volatile("cp.async.wait_group 1;")
#define CP_WAIT0()  asm volatile("cp.async.wait_group 0;")

__device__ __forceinline__ void ldm4(uint32_t* r, uint32_t addr) {
    asm volatile("ldmatrix.sync.aligned.m8n8.x4.shared.b16 {%0,%1,%2,%3}, [%4];"
                 : "=r"(r[0]), "=r"(r[1]), "=r"(r[2]), "=r"(r[3]) : "r"(addr));
}
__device__ __forceinline__ void mma16816(float* c, const uint32_t* a, uint32_t b0, uint32_t b1) {
    asm volatile("mma.sync.aligned.m16n8k16.row.col.f32.bf16.bf16.f32 "
                 "{%0,%1,%2,%3}, {%4,%5,%6,%7}, {%8,%9}, {%0,%1,%2,%3};"
                 : "+f"(c[0]), "+f"(c[1]), "+f"(c[2]), "+f"(c[3])
                 : "r"(a[0]), "r"(a[1]), "r"(a[2]), "r"(a[3]), "r"(b0), "r"(b1));
}

// smem tile geometry: 128 rows x 32 bf16, padded to 40 bf16 (80B) per row
#define ROW_B   80
#define TILE_B  (128 * ROW_B)         // 10240
#define STAGE_B (4 * TILE_B)          // AH, AL, BH, BL
#define NST 3
#define SMEM_DYN (NST * STAGE_B)      // 122880

struct Ptrs {
    const __nv_bfloat16 *aH, *aL, *bH, *bL;  // this thread's row, this thread's 16-elt half
    int asz;        // 16 (valid) or 0 (zfill pad row)
    uint32_t dst;   // smem byte offset within a tile for this thread
};

__device__ __forceinline__ void load_stage(uint32_t sm, int st, int koff, const Ptrs& p) {
    uint32_t b = sm + st * STAGE_B + p.dst;
    cp16(b + 0 * TILE_B,      p.aH + koff,     p.asz);
    cp16(b + 0 * TILE_B + 16, p.aH + koff + 8, p.asz);
    cp16(b + 1 * TILE_B,      p.aL + koff,     p.asz);
    cp16(b + 1 * TILE_B + 16, p.aL + koff + 8, p.asz);
    cp16(b + 2 * TILE_B,      p.bH + koff,     16);
    cp16(b + 2 * TILE_B + 16, p.bH + koff + 8, 16);
    cp16(b + 3 * TILE_B,      p.bL + koff,     16);
    cp16(b + 3 * TILE_B + 16, p.bL + koff + 8, 16);
}

// one BK=32 stage of 3-product bf16 mma; acc[16][4] covers 16 rows x 128 cols per warp
__device__ __forceinline__ void compute_stage(uint32_t sm, int st, float acc[16][4],
                                              uint32_t aoff, uint32_t boff) {
    uint32_t base = sm + st * STAGE_B;
    #pragma unroll
    for (int kk = 0; kk < 2; kk++) {
        uint32_t ka = kk * 32;                 // 16 bf16 = 32B per k-halfstep
        uint32_t a0[4], a1[4];
        ldm4(a0, base + 0 * TILE_B + aoff + ka);
        ldm4(a1, base + 1 * TILE_B + aoff + ka);
        #pragma unroll
        for (int nb = 0; nb < 8; nb++) {
            uint32_t bh[4], bl[4];
            ldm4(bh, base + 2 * TILE_B + boff + nb * (16 * ROW_B) + ka);
            ldm4(bl, base + 3 * TILE_B + boff + nb * (16 * ROW_B) + ka);
            mma16816(acc[2 * nb],     a0, bh[0], bh[1]);
            mma16816(acc[2 * nb + 1], a0, bh[2], bh[3]);
            mma16816(acc[2 * nb],     a0, bl[0], bl[1]);
            mma16816(acc[2 * nb + 1], a0, bl[2], bl[3]);
            mma16816(acc[2 * nb],     a1, bh[0], bh[1]);
            mma16816(acc[2 * nb + 1], a1, bh[2], bh[3]);
        }
    }
}

// ---------------- small kernels ----------------
__global__ void zero_cnt_kernel() {
    if (threadIdx.x < NUM_EXPERTS) g_cnt[threadIdx.x] = 0;
}
__global__ void prefix_kernel() {
    if (threadIdx.x == 0) {
        int s = 0;
        for (int e = 0; e < NUM_EXPERTS; e++) { g_off[e] = s; s += g_cnt[e]; }
    }
}
__global__ void split_kernel(const float* __restrict__ src, __nv_bfloat16* __restrict__ hi,
                             __nv_bfloat16* __restrict__ lo, size_t n4) {
    size_t i = (size_t)blockIdx.x * blockDim.x + threadIdx.x;
    size_t stride = (size_t)gridDim.x * blockDim.x;
    for (; i < n4; i += stride) {
        float4 v = ((const float4*)src)[i];
        __nv_bfloat16 h0 = __float2bfloat16(v.x), h1 = __float2bfloat16(v.y);
        __nv_bfloat16 h2 = __float2bfloat16(v.z), h3 = __float2bfloat16(v.w);
        __nv_bfloat162* hp = (__nv_bfloat162*)hi;
        __nv_bfloat162* lp = (__nv_bfloat162*)lo;
        hp[2 * i]     = __nv_bfloat162(h0, h1);
        hp[2 * i + 1] = __nv_bfloat162(h2, h3);
        lp[2 * i]     = __nv_bfloat162(__float2bfloat16(v.x - __bfloat162float(h0)),
                                       __float2bfloat16(v.y - __bfloat162float(h1)));
        lp[2 * i + 1] = __nv_bfloat162(__float2bfloat16(v.z - __bfloat162float(h2)),
                                       __float2bfloat16(v.w - __bfloat162float(h3)));
    }
}

// ---------------- router ----------------
__global__ void router_kernel(const float* __restrict__ x, const float* __restrict__ gate_w) {
    const int t = blockIdx.x;
    const int tid = threadIdx.x;
    __shared__ float xs[HIDDEN];
    __shared__ float part[256];
    __shared__ float lg[NUM_EXPERTS];

    for (int i = tid * 4; i < HIDDEN; i += 256 * 4)
        *(float4*)&xs[i] = *(const float4*)&x[(size_t)t * HIDDEN + i];
    __syncthreads();

    const int e = tid & 31;
    const int p = tid >> 5;
    const float* gw = gate_w + (size_t)e * HIDDEN + p * 192;
    const float* xp = xs + p * 192;
    float s = 0.0f;
    #pragma unroll 4
    for (int i = 0; i < 192; i++) s += xp[i] * gw[i];
    part[tid] = s;
    __syncthreads();

    if (tid < NUM_EXPERTS) {
        float l = 0.0f;
        #pragma unroll
        for (int q = 0; q < 8; q++) l += part[q * 32 + tid];
        lg[tid] = l;
    }
    __syncthreads();

    if (tid == 0) {
        float mx = -INFINITY;
        #pragma unroll
        for (int i = 0; i < NUM_EXPERTS; i++) mx = fmaxf(mx, lg[i]);
        float pr[NUM_EXPERTS];
        #pragma unroll
        for (int i = 0; i < NUM_EXPERTS; i++) pr[i] = expf(lg[i] - mx);
        int idx[TOP_K]; float w[TOP_K]; float ws = 0.0f;
        unsigned used = 0u;
        for (int k = 0; k < TOP_K; k++) {
            int bi = -1; float bv = -INFINITY;
            for (int i = 0; i < NUM_EXPERTS; i++)
                if (!(used >> i & 1u) && pr[i] > bv) { bv = pr[i]; bi = i; }
            used |= 1u << bi; idx[k] = bi; w[k] = bv; ws += bv;
        }
        float inv = 1.0f / ws;
        for (int k = 0; k < TOP_K; k++) {
            int slot = atomicAdd(&g_cnt[idx[k]], 1);
            g_tok[idx[k] * CAP + slot] = t;
            g_wt [idx[k] * CAP + slot] = w[k] * inv;
            g_pair[t * TOP_K + k] = (idx[k] << 20) | slot;
        }
    }
}

// ---------------- GEMM1: gu = X @ W13^T, h = silu(g)*u (bf16 split-3, HMMA) ----------------
__global__ void __launch_bounds__(256, 1) gemm1_kernel() {
    const int e = blockIdx.z;
    const int rows = g_cnt[e];
    const int rt = blockIdx.x;
    if (rt * 128 >= rows) return;
    const int ct = blockIdx.y;       // 0..7  -> cols ct*64 of g and of u
    const int base = g_off[e];

    extern __shared__ char smraw[];
    uint32_t sm = smem_u32(smraw);
    const int tid = threadIdx.x, wid = tid >> 5, lane = tid & 31;

    Ptrs p;
    {
        int r = tid >> 1;            // 0..127 : tile row this thread loads
        int half = tid & 1;          // 0/1 : 16-elt K half
        int arow = rt * 128 + r;
        int v = arow < rows;
        int tok = v ? g_tok[e * CAP + arow] : 0;
        p.aH = g_xh + (size_t)tok * HIDDEN + half * 16;
        p.aL = g_xl + (size_t)tok * HIDDEN + half * 16;
        p.asz = v ? 16 : 0;
        int grow = ct * 64 + (r & 63) + (r >> 6) * 512;     // n<64 -> g rows, n>=64 -> u rows
        p.bH = g_w13h + ((size_t)e * 1024 + grow) * HIDDEN + half * 16;
        p.bL = g_w13l + ((size_t)e * 1024 + grow) * HIDDEN + half * 16;
        p.dst = (uint32_t)(r * ROW_B + half * 32);
    }
    const uint32_t aoff = (wid * 16 + (lane & 15)) * ROW_B + (lane >> 4) * 16;
    const uint32_t boff = ((lane & 7) + ((lane >> 4) & 1) * 8) * ROW_B + ((lane >> 3) & 1) * 16;

    float acc[16][4];
    #pragma unroll
    for (int i = 0; i < 16; i++)
        #pragma unroll
        for (int j = 0; j < 4; j++) acc[i][j] = 0.0f;

    const int NCH = HIDDEN / 32;     // 48
    load_stage(sm, 0, 0, p);  CP_COMMIT();
    load_stage(sm, 1, 32, p); CP_COMMIT();
    for (int k = 0; k < NCH; k++) {
        CP_WAIT1();
        __syncthreads();
        if (k + 2 < NCH) load_stage(sm, (k + 2) % NST, (k + 2) * 32, p);
        CP_COMMIT();
        compute_stage(sm, k % NST, acc, aoff, boff);
    }

    // epilogue: cols 0..63 = g, 64..127 = u  ->  h = silu(g)*u, split to bf16 hi/lo
    int r0 = rt * 128 + wid * 16 + (lane >> 2);
    #pragma unroll
    for (int half = 0; half < 2; half++) {        // rows r0, r0+8
        int row = r0 + half * 8;
        if (row >= rows) continue;
        size_t hb = ((size_t)(base + row)) * INTER + ct * 64 + (lane & 3) * 2;
        #pragma unroll
        for (int nf = 0; nf < 8; nf++) {
            float g0 = acc[nf][2 * half],     u0 = acc[nf + 8][2 * half];
            float g1 = acc[nf][2 * half + 1], u1 = acc[nf + 8][2 * half + 1];
            float h0 = g0 * u0 / (1.0f + __expf(-g0));
            float h1 = g1 * u1 / (1.0f + __expf(-g1));
            __nv_bfloat16 hh0 = __float2bfloat16(h0), hh1 = __float2bfloat16(h1);
            *(__nv_bfloat162*)(g_hh + hb + nf * 8) = __nv_bfloat162(hh0, hh1);
            *(__nv_bfloat162*)(g_hl + hb + nf * 8) =
                __nv_bfloat162(__float2bfloat16(h0 - __bfloat162float(hh0)),
                               __float2bfloat16(h1 - __bfloat162float(hh1)));
        }
    }
}

// ---------------- GEMM2: y = wt * (h @ W2^T) (bf16 split-3, HMMA) ----------------
__global__ void __launch_bounds__(256, 1) gemm2_kernel() {
    const int e = blockIdx.z;
    const int rows = g_cnt[e];
    const int rt = blockIdx.x;
    if (rt * 128 >= rows) return;
    const int ct = blockIdx.y;       // 0..11 -> out cols ct*128
    const int base = g_off[e];

    extern __shared__ char smraw[];
    uint32_t sm = smem_u32(smraw);
    const int tid = threadIdx.x, wid = tid >> 5, lane = tid & 31;

    Ptrs p;
    {
        int r = tid >> 1;
        int half = tid & 1;
        int arow = rt * 128 + r;
        int v = arow < rows;
        size_t hrow = (size_t)(base + (v ? arow : 0));
        p.aH = g_hh + hrow * INTER + half * 16;
        p.aL = g_hl + hrow * INTER + half * 16;
        p.asz = v ? 16 : 0;
        size_t brow = (size_t)e * HIDDEN + ct * 128 + r;
        p.bH = g_w2h + brow * INTER + half * 16;
        p.bL = g_w2l + brow * INTER + half * 16;
        p.dst = (uint32_t)(r * ROW_B + half * 32);
    }
    const uint32_t aoff = (wid * 16 + (lane & 15)) * ROW_B + (lane >> 4) * 16;
    const uint32_t boff = ((lane & 7) + ((lane >> 4) & 1) * 8) * ROW_B + ((lane >> 3) & 1) * 16;

    float acc[16][4];
    #pragma unroll
    for (int i = 0; i < 16; i++)
        #pragma unroll
        for (int j = 0; j < 4; j++) acc[i][j] = 0.0f;

    const int NCH = INTER / 32;      // 16
    load_stage(sm, 0, 0, p);  CP_COMMIT();
    load_stage(sm, 1, 32, p); CP_COMMIT();
    for (int k = 0; k < NCH; k++) {
        CP_WAIT1();
        __syncthreads();
        if (k + 2 < NCH) load_stage(sm, (k + 2) % NST, (k + 2) * 32, p);
        CP_COMMIT();
        compute_stage(sm, k % NST, acc, aoff, boff);
    }

    int r0 = rt * 128 + wid * 16 + (lane >> 2);
    #pragma unroll
    for (int half = 0; half < 2; half++) {
        int row = r0 + half * 8;
        if (row >= rows) continue;
        float w = g_wt[e * CAP + row];
        float* yp = g_y + (size_t)(base + row) * HIDDEN + ct * 128 + (lane & 3) * 2;
        #pragma unroll
        for (int nf = 0; nf < 16; nf++) {
            float2 v;
            v.x = w * acc[nf][2 * half];
            v.y = w * acc[nf][2 * half + 1];
            *(float2*)(yp + nf * 8) = v;
        }
    }
}

// ---------------- gather: out[t] = sum_k y[row_k] ----------------
__global__ void gather_kernel(float* __restrict__ out) {
    const int t = blockIdx.x;
    int rowid[TOP_K];
    #pragma unroll
    for (int k = 0; k < TOP_K; k++) {
        int pp = g_pair[t * TOP_K + k];
        rowid[k] = g_off[pp >> 20] + (pp & 0xFFFFF);
    }
    for (int cc = threadIdx.x * 4; cc < HIDDEN; cc += blockDim.x * 4) {
        float4 acc = make_float4(0.f, 0.f, 0.f, 0.f);
        #pragma unroll
        for (int k = 0; k < TOP_K; k++) {
            float4 v = *(const float4*)(g_y + (size_t)rowid[k] * HIDDEN + cc);
            acc.x += v.x; acc.y += v.y; acc.z += v.z; acc.w += v.w;
        }
        *(float4*)(out + (size_t)t * HIDDEN + cc) = acc;
    }
}

// ---------------- launch ----------------
extern "C" void kernel_launch(void* const* d_in, const int* in_sizes, int n_in,
                              void* d_out, int out_size) {
    const float* x      = (const float*)d_in[0];
    const float* gate_w = (const float*)d_in[1];
    const float* w13    = (const float*)d_in[2];
    const float* w2     = (const float*)d_in[3];
    float* out = (float*)d_out;

    cudaFuncSetAttribute(gemm1_kernel, cudaFuncAttributeMaxDynamicSharedMemorySize, SMEM_DYN);
    cudaFuncSetAttribute(gemm2_kernel, cudaFuncAttributeMaxDynamicSharedMemorySize, SMEM_DYN);

    __nv_bfloat16 *xh, *xl, *w13h, *w13l, *w2h, *w2l;
    cudaGetSymbolAddress((void**)&xh,   g_xh);
    cudaGetSymbolAddress((void**)&xl,   g_xl);
    cudaGetSymbolAddress((void**)&w13h, g_w13h);
    cudaGetSymbolAddress((void**)&w13l, g_w13l);
    cudaGetSymbolAddress((void**)&w2h,  g_w2h);
    cudaGetSymbolAddress((void**)&w2l,  g_w2l);

    zero_cnt_kernel<<<1, 32>>>();
    router_kernel<<<T_TOT, 256>>>(x, gate_w);
    prefix_kernel<<<1, 32>>>();
    split_kernel<<<2048, 256>>>(x,   xh,   xl,   (size_t)T_TOT * HIDDEN / 4);
    split_kernel<<<4096, 256>>>(w13, w13h, w13l, (size_t)NUM_EXPERTS * 2 * INTER * HIDDEN / 4);
    split_kernel<<<4096, 256>>>(w2,  w2h,  w2l,  (size_t)NUM_EXPERTS * HIDDEN * INTER / 4);
    gemm1_kernel<<<dim3(T_TOT / 128, INTER / 64, NUM_EXPERTS), 256, SMEM_DYN>>>();
    gemm2_kernel<<<dim3(T_TOT / 128, HIDDEN / 128, NUM_EXPERTS), 256, SMEM_DYN>>>();
    gather_kernel<<<T_TOT, 128>>>(out);
}

// round 4
// speedup vs baseline: 1.9175x; 1.1059x over previous
#include <cuda_runtime.h>
#include <cuda_bf16.h>
#include <cstdint>
#include <math.h>

#define NUM_EXPERTS 32
#define TOP_K 8
#define HIDDEN 1536
#define INTER 512
#define T_TOT 8192
#define CAP 8192
#define ROWS_TOT (T_TOT * TOP_K)

// ---------------- device scratch ----------------
__device__ int   g_cnt[NUM_EXPERTS];
__device__ int   g_off[NUM_EXPERTS];
__device__ int   g_tok[NUM_EXPERTS * CAP];
__device__ float g_wt [NUM_EXPERTS * CAP];
__device__ int   g_pair[T_TOT * TOP_K];

__device__ __nv_bfloat16 g_xh[(size_t)T_TOT * HIDDEN];
__device__ __nv_bfloat16 g_xl[(size_t)T_TOT * HIDDEN];
__device__ __nv_bfloat16 g_w13h[(size_t)NUM_EXPERTS * 2 * INTER * HIDDEN];
__device__ __nv_bfloat16 g_w13l[(size_t)NUM_EXPERTS * 2 * INTER * HIDDEN];
__device__ __nv_bfloat16 g_w2h[(size_t)NUM_EXPERTS * HIDDEN * INTER];
__device__ __nv_bfloat16 g_w2l[(size_t)NUM_EXPERTS * HIDDEN * INTER];
__device__ __nv_bfloat16 g_hh[(size_t)ROWS_TOT * INTER];
__device__ __nv_bfloat16 g_hl[(size_t)ROWS_TOT * INTER];
__device__ float g_y[(size_t)ROWS_TOT * HIDDEN];

// ---------------- helpers ----------------
__device__ __forceinline__ uint32_t smem_u32(const void* p) {
    uint32_t a;
    asm("{ .reg .u64 t; cvta.to.shared.u64 t, %1; cvt.u32.u64 %0, t; }" : "=r"(a) : "l"(p));
    return a;
}
__device__ __forceinline__ void cp16(uint32_t dst, const void* src, int sz) {
    asm volatile("cp.async.cg.shared.global [%0], [%1], 16, %2;"
                 :: "r"(dst), "l"(__cvta_generic_to_global(src)), "r"(sz));
}
#define CP_COMMIT() asm volatile("cp.async.commit_group;")
#define CP_WAIT1()  asm volatile("cp.async.wait_group 1;")

__device__ __forceinline__ void ldm4(uint32_t* r, uint32_t addr) {
    asm volatile("ldmatrix.sync.aligned.m8n8.x4.shared.b16 {%0,%1,%2,%3}, [%4];"
                 : "=r"(r[0]), "=r"(r[1]), "=r"(r[2]), "=r"(r[3]) : "r"(addr));
}
__device__ __forceinline__ void mma16816(float* c, const uint32_t* a, uint32_t b0, uint32_t b1) {
    asm volatile("mma.sync.aligned.m16n8k16.row.col.f32.bf16.bf16.f32 "
                 "{%0,%1,%2,%3}, {%4,%5,%6,%7}, {%8,%9}, {%0,%1,%2,%3};"
                 : "+f"(c[0]), "+f"(c[1]), "+f"(c[2]), "+f"(c[3])
                 : "r"(a[0]), "r"(a[1]), "r"(a[2]), "r"(a[3]), "r"(b0), "r"(b1));
}

// smem: tiles 128 rows x 64 bf16 = 128B/row, chunk-XOR swizzle
#define TILE_B  16384
#define OFF_AH  0
#define OFF_AL  16384
#define OFF_BH  32768
#define OFF_BL  49152
#define STAGE_B 65536
#define NST 3
#define SMEM_DYN (NST * STAGE_B)   // 196608

struct LoadCtx {
    const __nv_bfloat16 *aH, *aL, *bH, *bL;  // row base + kc0*8 elements
    int asz;
    uint32_t dst[4];                         // swizzled smem offsets for 4 chunks
};

__device__ __forceinline__ void load_stage(uint32_t sm, int st, int koff, const LoadCtx& c) {
    uint32_t b = sm + st * STAGE_B;
    #pragma unroll
    for (int j = 0; j < 4; j++) {
        cp16(b + OFF_AH + c.dst[j], c.aH + koff + j * 8, c.asz);
        cp16(b + OFF_AL + c.dst[j], c.aL + koff + j * 8, c.asz);
        cp16(b + OFF_BH + c.dst[j], c.bH + koff + j * 8, 16);
        cp16(b + OFF_BL + c.dst[j], c.bL + koff + j * 8, 16);
    }
}

// one BK=64 stage; acc[2][8][4] = warp tile 32 rows x 64 cols
__device__ __forceinline__ void compute_stage(
        uint32_t sbase, int lane,
        const uint32_t arow[2], const uint32_t ar7[2],
        const uint32_t brow[4], const uint32_t br7[4],
        float acc[2][8][4]) {
    const uint32_t asel = lane >> 4;
    const uint32_t bsel = (lane >> 3) & 1;
    #pragma unroll
    for (int kk = 0; kk < 4; kk++) {
        uint32_t ah[2][4], al[2][4];
        #pragma unroll
        for (int mi = 0; mi < 2; mi++) {
            uint32_t ch = kk * 2 + asel;
            uint32_t ad = sbase + OFF_AH + arow[mi] + (((ch ^ ar7[mi]) & 7) << 4);
            ldm4(ah[mi], ad);
            ldm4(al[mi], ad + (OFF_AL - OFF_AH));
        }
        uint32_t bh[4][4], bl[4][4];
        #pragma unroll
        for (int q = 0; q < 4; q++) {
            uint32_t ch = kk * 2 + bsel;
            uint32_t bd = sbase + OFF_BH + brow[q] + (((ch ^ br7[q]) & 7) << 4);
            ldm4(bh[q], bd);
            ldm4(bl[q], bd + (OFF_BL - OFF_BH));
        }
        // 48 mma, reuse distance 16 (all accumulators independent within a pass)
        #pragma unroll
        for (int ni = 0; ni < 8; ni++)
            #pragma unroll
            for (int mi = 0; mi < 2; mi++)
                mma16816(acc[mi][ni], ah[mi], bh[ni >> 1][2 * (ni & 1)], bh[ni >> 1][2 * (ni & 1) + 1]);
        #pragma unroll
        for (int ni = 0; ni < 8; ni++)
            #pragma unroll
            for (int mi = 0; mi < 2; mi++)
                mma16816(acc[mi][ni], ah[mi], bl[ni >> 1][2 * (ni & 1)], bl[ni >> 1][2 * (ni & 1) + 1]);
        #pragma unroll
        for (int ni = 0; ni < 8; ni++)
            #pragma unroll
            for (int mi = 0; mi < 2; mi++)
                mma16816(acc[mi][ni], al[mi], bh[ni >> 1][2 * (ni & 1)], bh[ni >> 1][2 * (ni & 1) + 1]);
    }
}

// ---------------- small kernels ----------------
__global__ void zero_cnt_kernel() {
    if (threadIdx.x < NUM_EXPERTS) g_cnt[threadIdx.x] = 0;
}
__global__ void prefix_kernel() {
    if (threadIdx.x == 0) {
        int s = 0;
        for (int e = 0; e < NUM_EXPERTS; e++) { g_off[e] = s; s += g_cnt[e]; }
    }
}
__global__ void split_kernel(const float* __restrict__ src, __nv_bfloat16* __restrict__ hi,
                             __nv_bfloat16* __restrict__ lo, size_t n4) {
    size_t i = (size_t)blockIdx.x * blockDim.x + threadIdx.x;
    size_t stride = (size_t)gridDim.x * blockDim.x;
    for (; i < n4; i += stride) {
        float4 v = ((const float4*)src)[i];
        __nv_bfloat16 h0 = __float2bfloat16(v.x), h1 = __float2bfloat16(v.y);
        __nv_bfloat16 h2 = __float2bfloat16(v.z), h3 = __float2bfloat16(v.w);
        __nv_bfloat162* hp = (__nv_bfloat162*)hi;
        __nv_bfloat162* lp = (__nv_bfloat162*)lo;
        hp[2 * i]     = __nv_bfloat162(h0, h1);
        hp[2 * i + 1] = __nv_bfloat162(h2, h3);
        lp[2 * i]     = __nv_bfloat162(__float2bfloat16(v.x - __bfloat162float(h0)),
                                       __float2bfloat16(v.y - __bfloat162float(h1)));
        lp[2 * i + 1] = __nv_bfloat162(__float2bfloat16(v.z - __bfloat162float(h2)),
                                       __float2bfloat16(v.w - __bfloat162float(h3)));
    }
}

// ---------------- router ----------------
__global__ void router_kernel(const float* __restrict__ x, const float* __restrict__ gate_w) {
    const int t = blockIdx.x;
    const int tid = threadIdx.x;
    __shared__ float xs[HIDDEN];
    __shared__ float part[256];
    __shared__ float lg[NUM_EXPERTS];

    for (int i = tid * 4; i < HIDDEN; i += 256 * 4)
        *(float4*)&xs[i] = *(const float4*)&x[(size_t)t * HIDDEN + i];
    __syncthreads();

    const int e = tid & 31;
    const int p = tid >> 5;
    const float* gw = gate_w + (size_t)e * HIDDEN + p * 192;
    const float* xp = xs + p * 192;
    float s = 0.0f;
    #pragma unroll 4
    for (int i = 0; i < 192; i++) s += xp[i] * gw[i];
    part[tid] = s;
    __syncthreads();

    if (tid < NUM_EXPERTS) {
        float l = 0.0f;
        #pragma unroll
        for (int q = 0; q < 8; q++) l += part[q * 32 + tid];
        lg[tid] = l;
    }
    __syncthreads();

    if (tid == 0) {
        float mx = -INFINITY;
        #pragma unroll
        for (int i = 0; i < NUM_EXPERTS; i++) mx = fmaxf(mx, lg[i]);
        float pr[NUM_EXPERTS];
        #pragma unroll
        for (int i = 0; i < NUM_EXPERTS; i++) pr[i] = expf(lg[i] - mx);
        int idx[TOP_K]; float w[TOP_K]; float ws = 0.0f;
        unsigned used = 0u;
        for (int k = 0; k < TOP_K; k++) {
            int bi = -1; float bv = -INFINITY;
            for (int i = 0; i < NUM_EXPERTS; i++)
                if (!(used >> i & 1u) && pr[i] > bv) { bv = pr[i]; bi = i; }
            used |= 1u << bi; idx[k] = bi; w[k] = bv; ws += bv;
        }
        float inv = 1.0f / ws;
        for (int k = 0; k < TOP_K; k++) {
            int slot = atomicAdd(&g_cnt[idx[k]], 1);
            g_tok[idx[k] * CAP + slot] = t;
            g_wt [idx[k] * CAP + slot] = w[k] * inv;
            g_pair[t * TOP_K + k] = (idx[k] << 20) | slot;
        }
    }
}

// ---------------- GEMM1 ----------------
__global__ void __launch_bounds__(256, 1) gemm1_kernel() {
    const int e = blockIdx.z;
    const int rows = g_cnt[e];
    const int rt = blockIdx.x;
    if (rt * 128 >= rows) return;
    const int ct = blockIdx.y;     // 0..7 : g/u cols ct*64..+64
    const int base = g_off[e];

    extern __shared__ char smraw[];
    uint32_t sm = smem_u32(smraw);
    const int tid = threadIdx.x, wid = tid >> 5, lane = tid & 31;
    const int wm = wid >> 1, wn = wid & 1;

    LoadCtx c;
    {
        int r = tid >> 1;          // 0..127
        int kc0 = (tid & 1) * 4;   // first of 4 chunks
        int arow = rt * 128 + r;
        int v = arow < rows;
        int tok = v ? g_tok[e * CAP + arow] : 0;
        c.aH = g_xh + (size_t)tok * HIDDEN + kc0 * 8;
        c.aL = g_xl + (size_t)tok * HIDDEN + kc0 * 8;
        c.asz = v ? 16 : 0;
        // B row n=r: g/u interleaved per warp half
        int half = (r >> 5) & 1, wnn = r >> 6, cc = r & 31;
        int w13row = half * 512 + ct * 64 + wnn * 32 + cc;
        c.bH = g_w13h + ((size_t)e * 1024 + w13row) * HIDDEN + kc0 * 8;
        c.bL = g_w13l + ((size_t)e * 1024 + w13row) * HIDDEN + kc0 * 8;
        #pragma unroll
        for (int j = 0; j < 4; j++)
            c.dst[j] = (uint32_t)(r * 128 + (((kc0 + j) ^ (r & 7)) << 4));
    }

    uint32_t arow[2], ar7[2], brow[4], br7[4];
    #pragma unroll
    for (int mi = 0; mi < 2; mi++) {
        uint32_t r = wm * 32 + mi * 16 + (lane & 15);
        arow[mi] = r << 7; ar7[mi] = r & 7;
    }
    #pragma unroll
    for (int q = 0; q < 4; q++) {
        uint32_t r = wn * 64 + q * 16 + (lane & 7) + ((lane >> 4) & 1) * 8;
        brow[q] = r << 7; br7[q] = r & 7;
    }

    float acc[2][8][4];
    #pragma unroll
    for (int i = 0; i < 2; i++)
        #pragma unroll
        for (int j = 0; j < 8; j++)
            #pragma unroll
            for (int q = 0; q < 4; q++) acc[i][j][q] = 0.0f;

    const int NCH = HIDDEN / 64;   // 24
    load_stage(sm, 0, 0, c);  CP_COMMIT();
    load_stage(sm, 1, 64, c); CP_COMMIT();
    for (int k = 0; k < NCH; k++) {
        CP_WAIT1();
        __syncthreads();
        if (k + 2 < NCH) load_stage(sm, (k + 2) % NST, (k + 2) * 64, c);
        CP_COMMIT();
        compute_stage(sm + (k % NST) * STAGE_B, lane, arow, ar7, brow, br7, acc);
    }

    // epilogue: ni 0..3 = g, ni+4 = u
    const int lr = lane >> 2, lc = lane & 3;
    #pragma unroll
    for (int mi = 0; mi < 2; mi++)
        #pragma unroll
        for (int half = 0; half < 2; half++) {
            int row = rt * 128 + wm * 32 + mi * 16 + lr + half * 8;
            if (row >= rows) continue;
            size_t hb = ((size_t)(base + row)) * INTER + ct * 64 + wn * 32 + lc * 2;
            #pragma unroll
            for (int ni = 0; ni < 4; ni++) {
                float g0 = acc[mi][ni][2 * half],     u0 = acc[mi][ni + 4][2 * half];
                float g1 = acc[mi][ni][2 * half + 1], u1 = acc[mi][ni + 4][2 * half + 1];
                float h0 = g0 * u0 / (1.0f + __expf(-g0));
                float h1 = g1 * u1 / (1.0f + __expf(-g1));
                __nv_bfloat16 hh0 = __float2bfloat16(h0), hh1 = __float2bfloat16(h1);
                *(__nv_bfloat162*)(g_hh + hb + ni * 8) = __nv_bfloat162(hh0, hh1);
                *(__nv_bfloat162*)(g_hl + hb + ni * 8) =
                    __nv_bfloat162(__float2bfloat16(h0 - __bfloat162float(hh0)),
                                   __float2bfloat16(h1 - __bfloat162float(hh1)));
            }
        }
}

// ---------------- GEMM2 ----------------
__global__ void __launch_bounds__(256, 1) gemm2_kernel() {
    const int e = blockIdx.z;
    const int rows = g_cnt[e];
    const int rt = blockIdx.x;
    if (rt * 128 >= rows) return;
    const int ct = blockIdx.y;     // 0..11
    const int base = g_off[e];

    extern __shared__ char smraw[];
    uint32_t sm = smem_u32(smraw);
    const int tid = threadIdx.x, wid = tid >> 5, lane = tid & 31;
    const int wm = wid >> 1, wn = wid & 1;

    LoadCtx c;
    {
        int r = tid >> 1;
        int kc0 = (tid & 1) * 4;
        int arow = rt * 128 + r;
        int v = arow < rows;
        size_t hrow = (size_t)(base + (v ? arow : 0));
        c.aH = g_hh + hrow * INTER + kc0 * 8;
        c.aL = g_hl + hrow * INTER + kc0 * 8;
        c.asz = v ? 16 : 0;
        size_t brow_ = (size_t)e * HIDDEN + ct * 128 + r;
        c.bH = g_w2h + brow_ * INTER + kc0 * 8;
        c.bL = g_w2l + brow_ * INTER + kc0 * 8;
        #pragma unroll
        for (int j = 0; j < 4; j++)
            c.dst[j] = (uint32_t)(r * 128 + (((kc0 + j) ^ (r & 7)) << 4));
    }

    uint32_t arow[2], ar7[2], brow[4], br7[4];
    #pragma unroll
    for (int mi = 0; mi < 2; mi++) {
        uint32_t r = wm * 32 + mi * 16 + (lane & 15);
        arow[mi] = r << 7; ar7[mi] = r & 7;
    }
    #pragma unroll
    for (int q = 0; q < 4; q++) {
        uint32_t r = wn * 64 + q * 16 + (lane & 7) + ((lane >> 4) & 1) * 8;
        brow[q] = r << 7; br7[q] = r & 7;
    }

    float acc[2][8][4];
    #pragma unroll
    for (int i = 0; i < 2; i++)
        #pragma unroll
        for (int j = 0; j < 8; j++)
            #pragma unroll
            for (int q = 0; q < 4; q++) acc[i][j][q] = 0.0f;

    const int NCH = INTER / 64;    // 8
    load_stage(sm, 0, 0, c);  CP_COMMIT();
    load_stage(sm, 1, 64, c); CP_COMMIT();
    for (int k = 0; k < NCH; k++) {
        CP_WAIT1();
        __syncthreads();
        if (k + 2 < NCH) load_stage(sm, (k + 2) % NST, (k + 2) * 64, c);
        CP_COMMIT();
        compute_stage(sm + (k % NST) * STAGE_B, lane, arow, ar7, brow, br7, acc);
    }

    const int lr = lane >> 2, lc = lane & 3;
    #pragma unroll
    for (int mi = 0; mi < 2; mi++)
        #pragma unroll
        for (int half = 0; half < 2; half++) {
            int row = rt * 128 + wm * 32 + mi * 16 + lr + half * 8;
            if (row >= rows) continue;
            float w = g_wt[e * CAP + row];
            float* yp = g_y + (size_t)(base + row) * HIDDEN + ct * 128 + wn * 64 + lc * 2;
            #pragma unroll
            for (int ni = 0; ni < 8; ni++) {
                float2 v;
                v.x = w * acc[mi][ni][2 * half];
                v.y = w * acc[mi][ni][2 * half + 1];
                *(float2*)(yp + ni * 8) = v;
            }
        }
}

// ---------------- gather ----------------
__global__ void gather_kernel(float* __restrict__ out) {
    const int t = blockIdx.x;
    int rowid[TOP_K];
    #pragma unroll
    for (int k = 0; k < TOP_K; k++) {
        int pp = g_pair[t * TOP_K + k];
        rowid[k] = g_off[pp >> 20] + (pp & 0xFFFFF);
    }
    for (int cc = threadIdx.x * 4; cc < HIDDEN; cc += blockDim.x * 4) {
        float4 acc = make_float4(0.f, 0.f, 0.f, 0.f);
        #pragma unroll
        for (int k = 0; k < TOP_K; k++) {
            float4 v = *(const float4*)(g_y + (size_t)rowid[k] * HIDDEN + cc);
            acc.x += v.x; acc.y += v.y; acc.z += v.z; acc.w += v.w;
        }
        *(float4*)(out + (size_t)t * HIDDEN + cc) = acc;
    }
}

// ---------------- launch ----------------
extern "C" void kernel_launch(void* const* d_in, const int* in_sizes, int n_in,
                              void* d_out, int out_size) {
    const float* x      = (const float*)d_in[0];
    const float* gate_w = (const float*)d_in[1];
    const float* w13    = (const float*)d_in[2];
    const float* w2     = (const float*)d_in[3];
    float* out = (float*)d_out;

    cudaFuncSetAttribute(gemm1_kernel, cudaFuncAttributeMaxDynamicSharedMemorySize, SMEM_DYN);
    cudaFuncSetAttribute(gemm2_kernel, cudaFuncAttributeMaxDynamicSharedMemorySize, SMEM_DYN);

    __nv_bfloat16 *xh, *xl, *w13h, *w13l, *w2h, *w2l;
    cudaGetSymbolAddress((void**)&xh,   g_xh);
    cudaGetSymbolAddress((void**)&xl,   g_xl);
    cudaGetSymbolAddress((void**)&w13h, g_w13h);
    cudaGetSymbolAddress((void**)&w13l, g_w13l);
    cudaGetSymbolAddress((void**)&w2h,  g_w2h);
    cudaGetSymbolAddress((void**)&w2l,  g_w2l);

    zero_cnt_kernel<<<1, 32>>>();
    router_kernel<<<T_TOT, 256>>>(x, gate_w);
    prefix_kernel<<<1, 32>>>();
    split_kernel<<<2048, 256>>>(x,   xh,   xl,   (size_t)T_TOT * HIDDEN / 4);
    split_kernel<<<4096, 256>>>(w13, w13h, w13l, (size_t)NUM_EXPERTS * 2 * INTER * HIDDEN / 4);
    split_kernel<<<4096, 256>>>(w2,  w2h,  w2l,  (size_t)NUM_EXPERTS * HIDDEN * INTER / 4);
    gemm1_kernel<<<dim3(T_TOT / 128, INTER / 64, NUM_EXPERTS), 256, SMEM_DYN>>>();
    gemm2_kernel<<<dim3(T_TOT / 128, HIDDEN / 128, NUM_EXPERTS), 256, SMEM_DYN>>>();
    gather_kernel<<<T_TOT, 128>>>(out);
}